// round 6
// baseline (speedup 1.0000x reference)
#include <cuda_runtime.h>
#include <math.h>

#define N_OBS   256
#define N_Y     128
#define N_X     64
#define NITERS  150
#define EP_STRIDE 132   // row-major ep stride: 528B/row -> conflict-free LDS.128 across lanes

__device__ float g_ep[N_OBS * N_Y];             // ep row-major [t][j]
__device__ float g_yhat_fallback[N_OBS * N_Y];

struct SolverSmem {
    float ep[N_OBS * EP_STRIDE];                // 135168 B, row-major padded
    float zA[N_Y],  zB[N_Y];
    float yhA[N_Y], yhB[N_Y];
    float wA[N_OBS], wB[N_OBS];
    float partA[N_OBS], partB[N_OBS];
    float redIA[8], redWA[8], redIB[8], redWB[8];
    float cA, etaA, lamA;
    float cB, etaB, lamB;
};

// ---- packed f32x2 helpers (sm_103a) ---------------------------------------
__device__ __forceinline__ void fma2(unsigned long long& d,
                                     unsigned long long a,
                                     unsigned long long b) {
    asm("fma.rn.f32x2 %0, %1, %2, %0;" : "+l"(d) : "l"(a), "l"(b));
}
__device__ __forceinline__ unsigned long long pk2(float lo, float hi) {
    unsigned long long r;
    asm("mov.b64 %0, {%1, %2};" : "=l"(r) : "f"(lo), "f"(hi));
    return r;
}
__device__ __forceinline__ float upk_sum(unsigned long long v) {
    float lo, hi;
    asm("mov.b64 {%0, %1}, %2;" : "=f"(lo), "=f"(hi) : "l"(v));
    return lo + hi;
}

// ---------------------------------------------------------------------------
// Kernel 1: Y_hat = X @ W^T + b ; ep = Y - Y_hat (row-major)
// ---------------------------------------------------------------------------
__global__ void prep_kernel(const float* __restrict__ X,
                            const float* __restrict__ Y,
                            const float* __restrict__ W,
                            const float* __restrict__ b,
                            float* __restrict__ yhat_out) {
    __shared__ float Xs[N_X];
    __shared__ float Ws[N_Y * (N_X + 1)];
    const int t = blockIdx.x;
    const int i = threadIdx.x;

    if (i < N_X) Xs[i] = X[t * N_X + i];
    for (int idx = i; idx < N_Y * N_X; idx += blockDim.x) {
        int r = idx >> 6, cx = idx & 63;
        Ws[r * (N_X + 1) + cx] = W[idx];
    }
    __syncthreads();

    float acc = b[i];
#pragma unroll
    for (int x = 0; x < N_X; x++) acc += Xs[x] * Ws[i * (N_X + 1) + x];

    yhat_out[t * N_Y + i] = acc;
    g_ep[t * N_Y + i] = Y[t * N_Y + i] - acc;
}

// ---------------------------------------------------------------------------
// Warp-local: v = z - lr*(part[j]+part[j+128]-gamma*yh[j]); z = proj_simplex(v)
// ---------------------------------------------------------------------------
__device__ __forceinline__ void project_warp(const float* __restrict__ part,
                                             const float* __restrict__ yh,
                                             float* __restrict__ zz,
                                             float lr, float gamma) {
    const unsigned FULL = 0xffffffffu;
    const int lane = threadIdx.x & 31;

    float vorig[4], val[4];
#pragma unroll
    for (int r = 0; r < 4; r++) {
        const int j = r * 32 + lane;
        const float gz = part[j] + part[j + 128] - gamma * yh[j];
        vorig[r] = zz[j] - lr * gz;
        val[r] = vorig[r];
    }

    // Bitonic ascending sort over i = r*32 + lane.
#pragma unroll
    for (int kk = 2; kk <= 128; kk <<= 1) {
#pragma unroll
        for (int jj = kk >> 1; jj > 0; jj >>= 1) {
            if (jj >= 32) {
                const int rx = jj >> 5;
#pragma unroll
                for (int r = 0; r < 4; r++) {
                    if ((r & rx) == 0) {
                        const int r2 = r | rx;
                        const bool asc = (((r * 32) & kk) == 0);
                        const float a = val[r], b = val[r2];
                        const float lo = fminf(a, b), hi = fmaxf(a, b);
                        val[r]  = asc ? lo : hi;
                        val[r2] = asc ? hi : lo;
                    }
                }
            } else {
#pragma unroll
                for (int r = 0; r < 4; r++) {
                    const float pv = __shfl_xor_sync(FULL, val[r], jj);
                    const bool asc   = (((r * 32 + lane) & kk) == 0);
                    const bool lower = ((lane & jj) == 0);
                    val[r] = (lower == asc) ? fminf(val[r], pv) : fmaxf(val[r], pv);
                }
            }
        }
    }

    // 4 independent 32-lane inclusive scans (ILP), then carry combine.
    float x[4];
#pragma unroll
    for (int r = 0; r < 4; r++) x[r] = val[r];
#pragma unroll
    for (int d = 1; d < 32; d <<= 1) {
#pragma unroll
        for (int r = 0; r < 4; r++) {
            const float y = __shfl_up_sync(FULL, x[r], d);
            if (lane >= d) x[r] += y;
        }
    }
    float tot[4];
#pragma unroll
    for (int r = 0; r < 4; r++) tot[r] = __shfl_sync(FULL, x[r], 31);
    float off[4];
    off[0] = 0.0f;
    off[1] = tot[0];
    off[2] = tot[0] + tot[1];
    off[3] = off[2] + tot[2];
    const float Stot = off[3] + tot[3];

    float P[4];
#pragma unroll
    for (int r = 0; r < 4; r++) P[r] = x[r] + off[r];

    int rho = 0;
    float cssr[4];
#pragma unroll
    for (int r = 0; r < 4; r++) {
        const int i = r * 32 + lane;
        const float css = Stot - P[r] + val[r];
        cssr[r] = css;
        const bool cond = (val[r] + (1.0f - css) / (float)(128 - i)) > 0.0f;
        rho += __popc(__ballot_sync(FULL, cond));
    }

    const int it = 128 - rho;
    const int rt = it >> 5, lt = it & 31;
    const float sel = (rt == 0) ? cssr[0] : (rt == 1) ? cssr[1]
                    : (rt == 2) ? cssr[2] : cssr[3];
    const float css_t = __shfl_sync(FULL, sel, lt);
    const float theta = (css_t - 1.0f) / (float)rho;

#pragma unroll
    for (int r = 0; r < 4; r++) {
        const int j = r * 32 + lane;
        zz[j] = fmaxf(vorig[r] - theta, 0.0f);
    }
}

// ---------------------------------------------------------------------------
// Kernel 2: one CTA per TWO scenarios.
// Phase A: vectorized LDS.128 row reads (32/thread) + packed fma2.
// Phase B: column-layout register cache (loaded once) + broadcast w.
// ---------------------------------------------------------------------------
__global__ __launch_bounds__(256, 1)
void solver_kernel(const float* __restrict__ yhat_all,
                   const float* __restrict__ delta_p,
                   const float* __restrict__ gamma_p,
                   float* __restrict__ zout) {
    extern __shared__ char smem_raw[];
    SolverSmem* S = reinterpret_cast<SolverSmem*>(smem_raw);

    const int tid = threadIdx.x;
    const int sA = blockIdx.x * 2;
    const int sB = sA + 1;
    const float delta = *delta_p;
    const float gamma = *gamma_p;

    // Load ep row-major (coalesced global, padded shared rows)
    for (int idx = tid; idx < N_OBS * N_Y; idx += 256) {
        const int t = idx >> 7;
        const int j = idx & 127;
        S->ep[t * EP_STRIDE + j] = g_ep[idx];
    }
    if (tid < N_Y) {
        S->zA[tid] = 1.0f / (float)N_Y;
        S->zB[tid] = 1.0f / (float)N_Y;
        S->yhA[tid] = yhat_all[sA * N_Y + tid];
        S->yhB[tid] = yhat_all[sB * N_Y + tid];
    }
    if (tid == 0)  { S->cA = 0.0f; S->etaA = 0.0f; S->lamA = 0.1f; }
    if (tid == 32) { S->cB = 0.0f; S->etaB = 0.0f; S->lamB = 0.1f; }
    __syncthreads();

    // Column-layout register cache for Phase B: thread owns j = tid & 127,
    // t-half = tbase. ep2[q] = (ep[tbase+2q][j], ep[tbase+2q+1][j]).
    const int jown  = tid & 127;
    const int tbase = (tid >> 7) << 7;   // 0 or 128
    unsigned long long ep2[N_OBS / 4];   // 64 packed pairs
#pragma unroll
    for (int q = 0; q < N_OBS / 4; q++)
        ep2[q] = pk2(S->ep[(tbase + 2 * q)     * EP_STRIDE + jown],
                     S->ep[(tbase + 2 * q + 1) * EP_STRIDE + jown]);

    // Phase A row pointer: thread t's ep row, 16B-aligned (528 = 33*16).
    const ulonglong2* myrow =
        reinterpret_cast<const ulonglong2*>(&S->ep[tid * EP_STRIDE]);

    for (int k = 0; k < NITERS; k++) {
        const float lr = 0.05f / sqrtf(1.0f + (float)k);
        const float cA = S->cA, etaA = S->etaA, lamA = S->lamA;
        const float cB = S->cB, etaB = S->etaB, lamB = S->lamB;

        // ---- Phase A: r_t = ep_t . z - c (LDS.128 rows, packed fma2) ----
        unsigned long long aA0 = 0, aA1 = 0, aB0 = 0, aB1 = 0;
        {
            const ulonglong2* zA2 = reinterpret_cast<const ulonglong2*>(S->zA);
            const ulonglong2* zB2 = reinterpret_cast<const ulonglong2*>(S->zB);
#pragma unroll
            for (int q = 0; q < N_Y / 4; q++) {
                const ulonglong2 e  = myrow[q];
                const ulonglong2 za = zA2[q];
                const ulonglong2 zb = zB2[q];
                fma2(aA0, e.x, za.x);
                fma2(aA1, e.y, za.y);
                fma2(aB0, e.x, zb.x);
                fma2(aB1, e.y, zb.y);
            }
        }
        const float rA = upk_sum(aA0) + upk_sum(aA1) - cA;
        const float rB = upk_sum(aB0) + upk_sum(aB1) - cB;

        const float aAv = rA * rA - etaA;
        const float aBv = rB * rB - etaB;
        const float IA = (aAv > -lamA) ? 1.0f : ((aAv < -lamA) ? 0.0f : 0.5f);
        const float IB = (aBv > -lamB) ? 1.0f : ((aBv < -lamB) ? 0.0f : 0.5f);
        const float wAv = IA * 2.0f * rA * (1.0f / (float)N_OBS);
        const float wBv = IB * 2.0f * rB * (1.0f / (float)N_OBS);
        S->wA[tid] = wAv;
        S->wB[tid] = wBv;

        float sIA = IA, sWA = wAv, sIB = IB, sWB = wBv;
#pragma unroll
        for (int off = 16; off > 0; off >>= 1) {
            sIA += __shfl_down_sync(0xffffffffu, sIA, off);
            sWA += __shfl_down_sync(0xffffffffu, sWA, off);
            sIB += __shfl_down_sync(0xffffffffu, sIB, off);
            sWB += __shfl_down_sync(0xffffffffu, sWB, off);
        }
        if ((tid & 31) == 0) {
            const int wd = tid >> 5;
            S->redIA[wd] = sIA; S->redWA[wd] = sWA;
            S->redIB[wd] = sIB; S->redWB[wd] = sWB;
        }
        __syncthreads();   // B1: w + per-warp reductions visible

        // ---- Scalar updates (overlap with Phase B) ----
        if (tid == 0) {
            float SI = 0.0f, SW = 0.0f;
#pragma unroll
            for (int i = 0; i < 8; i++) { SI += S->redIA[i]; SW += S->redWA[i]; }
            S->cA   = cA + lr * SW;
            S->etaA = etaA - lr * (1.0f - SI * (1.0f / (float)N_OBS));
            S->lamA = fmaxf(lamA - lr * (delta - 1.0f + SI * (1.0f / (float)N_OBS)), 0.0f);
        }
        if (tid == 32) {
            float SI = 0.0f, SW = 0.0f;
#pragma unroll
            for (int i = 0; i < 8; i++) { SI += S->redIB[i]; SW += S->redWB[i]; }
            S->cB   = cB + lr * SW;
            S->etaB = etaB - lr * (1.0f - SI * (1.0f / (float)N_OBS));
            S->lamB = fmaxf(lamB - lr * (delta - 1.0f + SI * (1.0f / (float)N_OBS)), 0.0f);
        }

        // ---- Phase B: g_z[j] = sum_t w_t * ep[t][j] — registers + w broadcast ----
        {
            const ulonglong2* wa2 = reinterpret_cast<const ulonglong2*>(&S->wA[tbase]);
            const ulonglong2* wb2 = reinterpret_cast<const ulonglong2*>(&S->wB[tbase]);
            unsigned long long pA0 = 0, pA1 = 0, pB0 = 0, pB1 = 0;
#pragma unroll
            for (int q = 0; q < 32; q++) {
                const ulonglong2 wa = wa2[q];
                const ulonglong2 wb = wb2[q];
                fma2(pA0, ep2[2 * q],     wa.x);
                fma2(pA1, ep2[2 * q + 1], wa.y);
                fma2(pB0, ep2[2 * q],     wb.x);
                fma2(pB1, ep2[2 * q + 1], wb.y);
            }
            S->partA[tid] = upk_sum(pA0) + upk_sum(pA1);
            S->partB[tid] = upk_sum(pB0) + upk_sum(pB1);
        }
        __syncthreads();   // B2: part visible

        const int wid = tid >> 5;
        if (wid == 0)      project_warp(S->partA, S->yhA, S->zA, lr, gamma);
        else if (wid == 1) project_warp(S->partB, S->yhB, S->zB, lr, gamma);
        __syncthreads();   // B3: new z visible
    }

    if (tid < 128) {
        zout[sA * N_Y + tid] = S->zA[tid];
    } else {
        zout[sB * N_Y + (tid - 128)] = S->zB[tid - 128];
    }
}

// ---------------------------------------------------------------------------
extern "C" void kernel_launch(void* const* d_in, const int* in_sizes, int n_in,
                              void* d_out, int out_size) {
    const float* X     = (const float*)d_in[0];
    const float* Y     = (const float*)d_in[1];
    const float* W     = (const float*)d_in[2];
    const float* b     = (const float*)d_in[3];
    const float* delta = (const float*)d_in[4];
    const float* gamma = (const float*)d_in[5];

    float* out = (float*)d_out;
    float* zout = out;
    float* yhat;
    if (out_size >= 2 * N_OBS * N_Y) {
        yhat = out + N_OBS * N_Y;
    } else {
        void* p = nullptr;
        cudaGetSymbolAddress(&p, g_yhat_fallback);
        yhat = (float*)p;
    }

    static const size_t smem_bytes = sizeof(SolverSmem);
    cudaFuncSetAttribute(solver_kernel,
                         cudaFuncAttributeMaxDynamicSharedMemorySize,
                         (int)smem_bytes);

    prep_kernel<<<N_OBS, N_Y>>>(X, Y, W, b, yhat);
    solver_kernel<<<N_OBS / 2, 256, smem_bytes>>>(yhat, delta, gamma, zout);
}

// round 7
// speedup vs baseline: 1.1120x; 1.1120x over previous
#include <cuda_runtime.h>
#include <math.h>

#define N_OBS   256
#define N_Y     128
#define N_X     64
#define NITERS  150
#define EP_STRIDE 132   // row-major ep stride: 528B/row -> conflict-free LDS.128 across lanes

__device__ float g_ep[N_OBS * N_Y];             // ep row-major [t][j]
__device__ float g_yhat_fallback[N_OBS * N_Y];

struct SolverSmem {
    float ep[N_OBS * EP_STRIDE];                // 135168 B, row-major padded
    float zA[N_Y],  zB[N_Y];
    float yhA[N_Y], yhB[N_Y];
    float wA[N_OBS], wB[N_OBS];
    float partA[N_OBS], partB[N_OBS];
    float redIA[8], redWA[8], redIB[8], redWB[8];
    float cA, etaA, lamA;
    float cB, etaB, lamB;
};

// ---- packed f32x2 helpers (sm_103a) ---------------------------------------
__device__ __forceinline__ void fma2(unsigned long long& d,
                                     unsigned long long a,
                                     unsigned long long b) {
    asm("fma.rn.f32x2 %0, %1, %2, %0;" : "+l"(d) : "l"(a), "l"(b));
}
__device__ __forceinline__ unsigned long long pk2(float lo, float hi) {
    unsigned long long r;
    asm("mov.b64 %0, {%1, %2};" : "=l"(r) : "f"(lo), "f"(hi));
    return r;
}
__device__ __forceinline__ float upk_sum(unsigned long long v) {
    float lo, hi;
    asm("mov.b64 {%0, %1}, %2;" : "=f"(lo), "=f"(hi) : "l"(v));
    return lo + hi;
}

// ---------------------------------------------------------------------------
// Kernel 1: Y_hat = X @ W^T + b ; ep = Y - Y_hat (row-major)
// ---------------------------------------------------------------------------
__global__ void prep_kernel(const float* __restrict__ X,
                            const float* __restrict__ Y,
                            const float* __restrict__ W,
                            const float* __restrict__ b,
                            float* __restrict__ yhat_out) {
    __shared__ float Xs[N_X];
    __shared__ float Ws[N_Y * (N_X + 1)];
    const int t = blockIdx.x;
    const int i = threadIdx.x;

    if (i < N_X) Xs[i] = X[t * N_X + i];
    for (int idx = i; idx < N_Y * N_X; idx += blockDim.x) {
        int r = idx >> 6, cx = idx & 63;
        Ws[r * (N_X + 1) + cx] = W[idx];
    }
    __syncthreads();

    float acc = b[i];
#pragma unroll
    for (int x = 0; x < N_X; x++) acc += Xs[x] * Ws[i * (N_X + 1) + x];

    yhat_out[t * N_Y + i] = acc;
    g_ep[t * N_Y + i] = Y[t * N_Y + i] - acc;
}

// ---------------------------------------------------------------------------
// Block-layout warp-local simplex projection of 128 values.
// Element i = lane*4 + r. Strides 1,2 register-local; only 15 SHFL levels.
// Computes v = z - lr*(part[j]+part[j+128]-gamma*yh[j]); z = proj_simplex(v).
// ---------------------------------------------------------------------------
__device__ __forceinline__ void cswap(float& a, float& b, bool asc) {
    const float lo = fminf(a, b), hi = fmaxf(a, b);
    a = asc ? lo : hi;
    b = asc ? hi : lo;
}

__device__ __forceinline__ void project_warp_blk(const float* __restrict__ part,
                                                 const float* __restrict__ yh,
                                                 float* __restrict__ zz,
                                                 float lr, float gamma) {
    const unsigned FULL = 0xffffffffu;
    const int lane = threadIdx.x & 31;

    const float4 p0 = *reinterpret_cast<const float4*>(&part[lane * 4]);
    const float4 p1 = *reinterpret_cast<const float4*>(&part[128 + lane * 4]);
    const float4 yv = *reinterpret_cast<const float4*>(&yh[lane * 4]);
    const float4 zv = *reinterpret_cast<const float4*>(&zz[lane * 4]);

    float vorig[4], val[4];
    vorig[0] = zv.x - lr * (p0.x + p1.x - gamma * yv.x);
    vorig[1] = zv.y - lr * (p0.y + p1.y - gamma * yv.y);
    vorig[2] = zv.z - lr * (p0.z + p1.z - gamma * yv.z);
    vorig[3] = zv.w - lr * (p0.w + p1.w - gamma * yv.w);
#pragma unroll
    for (int r = 0; r < 4; r++) val[r] = vorig[r];

    // ---- bitonic ascending sort over i = lane*4 + r ----
    // kk=2 (jj=1, reg)
    cswap(val[0], val[1], true);
    cswap(val[2], val[3], false);
    // kk=4 (jj=2,1 reg)
    {
        const bool a = (lane & 1) == 0;
        cswap(val[0], val[2], a); cswap(val[1], val[3], a);
        cswap(val[0], val[1], a); cswap(val[2], val[3], a);
    }

#define SHFL_LEVEL(ls, asc) do {                                         \
        const bool _low = (lane & (ls)) == 0;                            \
        _Pragma("unroll")                                                \
        for (int r = 0; r < 4; r++) {                                    \
            const float pv = __shfl_xor_sync(FULL, val[r], (ls));        \
            val[r] = (_low == (asc)) ? fminf(val[r], pv)                 \
                                     : fmaxf(val[r], pv);                \
        }                                                                \
    } while (0)

#define REG_TAIL(asc) do {                                               \
        cswap(val[0], val[2], (asc)); cswap(val[1], val[3], (asc));      \
        cswap(val[0], val[1], (asc)); cswap(val[2], val[3], (asc));      \
    } while (0)

    { const bool a = (lane & 2)  == 0; SHFL_LEVEL(1, a); REG_TAIL(a); }                                   // kk=8
    { const bool a = (lane & 4)  == 0; SHFL_LEVEL(2, a); SHFL_LEVEL(1, a); REG_TAIL(a); }                 // kk=16
    { const bool a = (lane & 8)  == 0; SHFL_LEVEL(4, a); SHFL_LEVEL(2, a); SHFL_LEVEL(1, a); REG_TAIL(a);} // kk=32
    { const bool a = (lane & 16) == 0; SHFL_LEVEL(8, a); SHFL_LEVEL(4, a); SHFL_LEVEL(2, a);
      SHFL_LEVEL(1, a); REG_TAIL(a); }                                                                    // kk=64
    { SHFL_LEVEL(16, true); SHFL_LEVEL(8, true); SHFL_LEVEL(4, true); SHFL_LEVEL(2, true);
      SHFL_LEVEL(1, true); REG_TAIL(true); }                                                              // kk=128

#undef SHFL_LEVEL
#undef REG_TAIL

    // ---- inclusive prefix sum over sorted values (block layout) ----
    const float s0 = val[0];
    const float s1 = s0 + val[1];
    const float s2 = s1 + val[2];
    const float s3 = s2 + val[3];
    float incl = s3;
#pragma unroll
    for (int d = 1; d < 32; d <<= 1) {
        const float y = __shfl_up_sync(FULL, incl, d);
        if (lane >= d) incl += y;
    }
    const float prefix = incl - s3;
    const float Stot = __shfl_sync(FULL, incl, 31);
    const float P[4] = { s0 + prefix, s1 + prefix, s2 + prefix, s3 + prefix };

    // css at sorted position i (descending cumsum): css = Stot - P[i] + u[i]
    int rho = 0;
    float cssr[4];
#pragma unroll
    for (int r = 0; r < 4; r++) {
        const int i = lane * 4 + r;
        const float css = Stot - P[r] + val[r];
        cssr[r] = css;
        const bool cond = (val[r] + (1.0f - css) / (float)(128 - i)) > 0.0f;
        rho += __popc(__ballot_sync(FULL, cond));
    }

    const int it = 128 - rho;          // sorted index holding css[rho-1]
    const int Lt = it >> 2, rt = it & 3;
    const float sel = (rt == 0) ? cssr[0] : (rt == 1) ? cssr[1]
                    : (rt == 2) ? cssr[2] : cssr[3];
    const float css_t = __shfl_sync(FULL, sel, Lt);
    const float theta = (css_t - 1.0f) / (float)rho;

    float4 zo;
    zo.x = fmaxf(vorig[0] - theta, 0.0f);
    zo.y = fmaxf(vorig[1] - theta, 0.0f);
    zo.z = fmaxf(vorig[2] - theta, 0.0f);
    zo.w = fmaxf(vorig[3] - theta, 0.0f);
    *reinterpret_cast<float4*>(&zz[lane * 4]) = zo;
}

// ---------------------------------------------------------------------------
// Kernel 2: one CTA per TWO scenarios.
// Phase A: LDS.128 rows + packed fma2. Phase B: column register cache + bcast w.
// Projection (warps 0,1) and scalar updates (warp 2) share the B2->B3 window.
// ---------------------------------------------------------------------------
__global__ __launch_bounds__(256, 1)
void solver_kernel(const float* __restrict__ yhat_all,
                   const float* __restrict__ delta_p,
                   const float* __restrict__ gamma_p,
                   float* __restrict__ zout) {
    extern __shared__ char smem_raw[];
    SolverSmem* S = reinterpret_cast<SolverSmem*>(smem_raw);

    const int tid = threadIdx.x;
    const int sA = blockIdx.x * 2;
    const int sB = sA + 1;
    const float delta = *delta_p;
    const float gamma = *gamma_p;

    for (int idx = tid; idx < N_OBS * N_Y; idx += 256) {
        const int t = idx >> 7;
        const int j = idx & 127;
        S->ep[t * EP_STRIDE + j] = g_ep[idx];
    }
    if (tid < N_Y) {
        S->zA[tid] = 1.0f / (float)N_Y;
        S->zB[tid] = 1.0f / (float)N_Y;
        S->yhA[tid] = yhat_all[sA * N_Y + tid];
        S->yhB[tid] = yhat_all[sB * N_Y + tid];
    }
    if (tid == 0)  { S->cA = 0.0f; S->etaA = 0.0f; S->lamA = 0.1f; }
    if (tid == 32) { S->cB = 0.0f; S->etaB = 0.0f; S->lamB = 0.1f; }
    __syncthreads();

    // Column-layout register cache for Phase B: thread owns j = tid & 127,
    // t-half = tbase. ep2[q] = (ep[tbase+2q][j], ep[tbase+2q+1][j]).
    const int jown  = tid & 127;
    const int tbase = (tid >> 7) << 7;   // 0 or 128
    unsigned long long ep2[N_OBS / 4];   // 64 packed pairs
#pragma unroll
    for (int q = 0; q < N_OBS / 4; q++)
        ep2[q] = pk2(S->ep[(tbase + 2 * q)     * EP_STRIDE + jown],
                     S->ep[(tbase + 2 * q + 1) * EP_STRIDE + jown]);

    // Phase A row pointer: thread t's ep row, 16B-aligned (528 = 33*16).
    const ulonglong2* myrow =
        reinterpret_cast<const ulonglong2*>(&S->ep[tid * EP_STRIDE]);

    for (int k = 0; k < NITERS; k++) {
        const float lr = 0.05f / sqrtf(1.0f + (float)k);
        const float cA = S->cA, etaA = S->etaA, lamA = S->lamA;
        const float cB = S->cB, etaB = S->etaB, lamB = S->lamB;

        // ---- Phase A: r_t = ep_t . z - c (LDS.128 rows, packed fma2) ----
        unsigned long long aA0 = 0, aA1 = 0, aB0 = 0, aB1 = 0;
        {
            const ulonglong2* zA2 = reinterpret_cast<const ulonglong2*>(S->zA);
            const ulonglong2* zB2 = reinterpret_cast<const ulonglong2*>(S->zB);
#pragma unroll
            for (int q = 0; q < N_Y / 4; q++) {
                const ulonglong2 e  = myrow[q];
                const ulonglong2 za = zA2[q];
                const ulonglong2 zb = zB2[q];
                fma2(aA0, e.x, za.x);
                fma2(aA1, e.y, za.y);
                fma2(aB0, e.x, zb.x);
                fma2(aB1, e.y, zb.y);
            }
        }
        const float rA = upk_sum(aA0) + upk_sum(aA1) - cA;
        const float rB = upk_sum(aB0) + upk_sum(aB1) - cB;

        const float aAv = rA * rA - etaA;
        const float aBv = rB * rB - etaB;
        const float IA = (aAv > -lamA) ? 1.0f : ((aAv < -lamA) ? 0.0f : 0.5f);
        const float IB = (aBv > -lamB) ? 1.0f : ((aBv < -lamB) ? 0.0f : 0.5f);
        const float wAv = IA * 2.0f * rA * (1.0f / (float)N_OBS);
        const float wBv = IB * 2.0f * rB * (1.0f / (float)N_OBS);
        S->wA[tid] = wAv;
        S->wB[tid] = wBv;

        float sIA = IA, sWA = wAv, sIB = IB, sWB = wBv;
#pragma unroll
        for (int off = 16; off > 0; off >>= 1) {
            sIA += __shfl_down_sync(0xffffffffu, sIA, off);
            sWA += __shfl_down_sync(0xffffffffu, sWA, off);
            sIB += __shfl_down_sync(0xffffffffu, sIB, off);
            sWB += __shfl_down_sync(0xffffffffu, sWB, off);
        }
        if ((tid & 31) == 0) {
            const int wd = tid >> 5;
            S->redIA[wd] = sIA; S->redWA[wd] = sWA;
            S->redIB[wd] = sIB; S->redWB[wd] = sWB;
        }
        __syncthreads();   // B1: w + per-warp reductions visible

        // ---- Phase B: g_z[j] = sum_t w_t * ep[t][j] — registers + w broadcast ----
        {
            const ulonglong2* wa2 = reinterpret_cast<const ulonglong2*>(&S->wA[tbase]);
            const ulonglong2* wb2 = reinterpret_cast<const ulonglong2*>(&S->wB[tbase]);
            unsigned long long pA0 = 0, pA1 = 0, pB0 = 0, pB1 = 0;
#pragma unroll
            for (int q = 0; q < 32; q++) {
                const ulonglong2 wa = wa2[q];
                const ulonglong2 wb = wb2[q];
                fma2(pA0, ep2[2 * q],     wa.x);
                fma2(pA1, ep2[2 * q + 1], wa.y);
                fma2(pB0, ep2[2 * q],     wb.x);
                fma2(pB1, ep2[2 * q + 1], wb.y);
            }
            S->partA[tid] = upk_sum(pA0) + upk_sum(pA1);
            S->partB[tid] = upk_sum(pB0) + upk_sum(pB1);
        }
        __syncthreads();   // B2: part visible

        // ---- B2->B3 window: projections (warps 0,1) + scalar updates (warp 2) ----
        const int wid = tid >> 5;
        if (wid == 0) {
            project_warp_blk(S->partA, S->yhA, S->zA, lr, gamma);
        } else if (wid == 1) {
            project_warp_blk(S->partB, S->yhB, S->zB, lr, gamma);
        } else if (wid == 2) {
            const int lane = tid & 31;
            if (lane == 0) {
                float SI = 0.0f, SW = 0.0f;
#pragma unroll
                for (int i = 0; i < 8; i++) { SI += S->redIA[i]; SW += S->redWA[i]; }
                S->cA   = cA + lr * SW;
                S->etaA = etaA - lr * (1.0f - SI * (1.0f / (float)N_OBS));
                S->lamA = fmaxf(lamA - lr * (delta - 1.0f + SI * (1.0f / (float)N_OBS)), 0.0f);
            } else if (lane == 1) {
                float SI = 0.0f, SW = 0.0f;
#pragma unroll
                for (int i = 0; i < 8; i++) { SI += S->redIB[i]; SW += S->redWB[i]; }
                S->cB   = cB + lr * SW;
                S->etaB = etaB - lr * (1.0f - SI * (1.0f / (float)N_OBS));
                S->lamB = fmaxf(lamB - lr * (delta - 1.0f + SI * (1.0f / (float)N_OBS)), 0.0f);
            }
        }
        __syncthreads();   // B3: new z + scalars visible
    }

    if (tid < 128) {
        zout[sA * N_Y + tid] = S->zA[tid];
    } else {
        zout[sB * N_Y + (tid - 128)] = S->zB[tid - 128];
    }
}

// ---------------------------------------------------------------------------
extern "C" void kernel_launch(void* const* d_in, const int* in_sizes, int n_in,
                              void* d_out, int out_size) {
    const float* X     = (const float*)d_in[0];
    const float* Y     = (const float*)d_in[1];
    const float* W     = (const float*)d_in[2];
    const float* b     = (const float*)d_in[3];
    const float* delta = (const float*)d_in[4];
    const float* gamma = (const float*)d_in[5];

    float* out = (float*)d_out;
    float* zout = out;
    float* yhat;
    if (out_size >= 2 * N_OBS * N_Y) {
        yhat = out + N_OBS * N_Y;
    } else {
        void* p = nullptr;
        cudaGetSymbolAddress(&p, g_yhat_fallback);
        yhat = (float*)p;
    }

    static const size_t smem_bytes = sizeof(SolverSmem);
    cudaFuncSetAttribute(solver_kernel,
                         cudaFuncAttributeMaxDynamicSharedMemorySize,
                         (int)smem_bytes);

    prep_kernel<<<N_OBS, N_Y>>>(X, Y, W, b, yhat);
    solver_kernel<<<N_OBS / 2, 256, smem_bytes>>>(yhat, delta, gamma, zout);
}